// round 7
// baseline (speedup 1.0000x reference)
#include <cuda_runtime.h>
#include <math.h>

// ---------------------------------------------------------------------------
// PolicyGradientLoss: out = mean( nll(w,a) * (D - mean D) )
//   D[t] = sum_{k>=t} gamma^{k-t} r[k]
//   nll[t] = logsumexp(w[t,:]) - w[t, a[t]]
// Identity: mean(nll*(D-mD)) = (S_pd - S_d*S_n/T)/T
// ep_as is int32 on device.
//
// R7: weight rows staged through smem with coalesced loads (kills the
// 72B-strided L1 wavefront blowup seen in R6 ncu), gather served from smem.
// ---------------------------------------------------------------------------

#define GAMMA 0.99f
#define BT 256                         // threads per block
#define FPT 8                          // rows per thread (scan) == tiles per block
#define FCHUNK (BT * FPT)              // 2048 rows per block
#define MAXT (1 << 22)
#define MAXC (MAXT / FCHUNK)

#define AH 9                           // A/2 float2 per row (A=18)

static __device__ float  g_cg[MAXC];
static __device__ float  g_cs[MAXC];
static __device__ float  g_cin[MAXC];
static __device__ double g_acc[3];     // [0]=sum d, [1]=sum nll, [2]=sum nll*d

__device__ __forceinline__ float gamma8() {
    float g2 = GAMMA * GAMMA; float g4 = g2 * g2; return g4 * g4;
}

__device__ __forceinline__ void load8(const float* __restrict__ r, long long base,
                                      long long T, float rv[FPT]) {
    if (base + FPT <= T) {
        const float4* p = reinterpret_cast<const float4*>(r + base);
        float4 v0 = p[0], v1 = p[1];
        rv[0]=v0.x; rv[1]=v0.y; rv[2]=v0.z; rv[3]=v0.w;
        rv[4]=v1.x; rv[5]=v1.y; rv[6]=v1.z; rv[7]=v1.w;
    } else {
        #pragma unroll
        for (int j = 0; j < FPT; j++)
            rv[j] = (base + j < T) ? r[base + j] : 0.0f;
    }
}

// Warp inclusive suffix scan of affine (g,s); lane i -> aggregate [i..31].
__device__ __forceinline__ void warp_suffix_incl(float& g, float& s) {
    int lane = threadIdx.x & 31;
    #pragma unroll
    for (int off = 1; off < 32; off <<= 1) {
        float g2 = __shfl_down_sync(0xffffffffu, g, off);
        float s2 = __shfl_down_sync(0xffffffffu, s, off);
        if (lane + off < 32) { s = s + g * s2; g = g * g2; }
    }
}

// Carry value entering this thread's segment given block-incoming carry cin.
// Leaves shg/shs holding warp aggregates.
__device__ __forceinline__ float thread_carry(float gseg, float sseg, float cin,
                                              float* shg, float* shs) {
    int lane = threadIdx.x & 31, wid = threadIdx.x >> 5;
    int nw = blockDim.x >> 5;
    float g = gseg, s = sseg;
    warp_suffix_incl(g, s);
    float ge = __shfl_down_sync(0xffffffffu, g, 1);
    float se = __shfl_down_sync(0xffffffffu, s, 1);
    if (lane == 31) { ge = 1.0f; se = 0.0f; }
    if (lane == 0) { shg[wid] = g; shs[wid] = s; }
    __syncthreads();
    float gw = 1.0f, sw = 0.0f;
    for (int wv = wid + 1; wv < nw; wv++) { sw = sw + gw * shs[wv]; gw = gw * shg[wv]; }
    return se + ge * (sw + gw * cin);
}

__device__ __forceinline__ void block_reduce3(double a, double b, double c) {
    #pragma unroll
    for (int o = 16; o > 0; o >>= 1) {
        a += __shfl_down_sync(0xffffffffu, a, o);
        b += __shfl_down_sync(0xffffffffu, b, o);
        c += __shfl_down_sync(0xffffffffu, c, o);
    }
    __shared__ double sa[8], sb[8], sc[8];
    int lane = threadIdx.x & 31, wid = threadIdx.x >> 5;
    if (lane == 0) { sa[wid] = a; sb[wid] = b; sc[wid] = c; }
    __syncthreads();
    if (wid == 0) {
        int nw = blockDim.x >> 5;
        a = (lane < nw) ? sa[lane] : 0.0;
        b = (lane < nw) ? sb[lane] : 0.0;
        c = (lane < nw) ? sc[lane] : 0.0;
        #pragma unroll
        for (int o = 4; o > 0; o >>= 1) {
            a += __shfl_down_sync(0xffffffffu, a, o);
            b += __shfl_down_sync(0xffffffffu, b, o);
            c += __shfl_down_sync(0xffffffffu, c, o);
        }
        if (lane == 0) {
            atomicAdd(&g_acc[0], a);
            atomicAdd(&g_acc[1], b);
            atomicAdd(&g_acc[2], c);
        }
    }
}

// Phase 1: per-chunk (g, s) aggregates
__global__ void __launch_bounds__(BT) k_agg(const float* __restrict__ r, long long T) {
    __shared__ float shg[BT / 32], shs[BT / 32];
    int tid = threadIdx.x;
    long long base = (long long)blockIdx.x * FCHUNK + (long long)tid * FPT;
    float rv[FPT];
    load8(r, base, T, rv);
    int cnt = (int)max(0LL, min((long long)FPT, T - base));
    float carry = 0.0f;
    #pragma unroll
    for (int j = FPT - 1; j >= 0; --j) carry = carry * GAMMA + rv[j];
    float gseg = (cnt == FPT) ? gamma8() : __powf(GAMMA, (float)cnt);
    (void)thread_carry(gseg, carry, 0.0f, shg, shs);
    __syncthreads();
    if (tid == 0) {
        int nw = blockDim.x >> 5;
        float g = 1.0f, s = 0.0f;
        for (int wv = 0; wv < nw; wv++) { s = s + g * shs[wv]; g = g * shg[wv]; }
        g_cg[blockIdx.x] = g; g_cs[blockIdx.x] = s;
    }
}

// Phase 2: suffix scan over chunk aggregates; also zeroes accumulators.
__global__ void __launch_bounds__(BT) k_scan2(int nchunk) {
    __shared__ float shg[BT / 32], shs[BT / 32];
    int tid = threadIdx.x;
    if (tid == 0) { g_acc[0] = 0.0; g_acc[1] = 0.0; g_acc[2] = 0.0; }
    int kc = (nchunk + BT - 1) / BT;
    int lo = tid * kc;
    int hi = min(lo + kc, nchunk);
    float g = 1.0f, s = 0.0f;
    for (int c = lo; c < hi; c++) { s = s + g * g_cs[c]; g = g * g_cg[c]; }
    float carry = thread_carry(g, s, 0.0f, shg, shs);
    for (int c = hi - 1; c >= lo; --c) {
        g_cin[c] = carry;
        carry = g_cs[c] + g_cg[c] * carry;
    }
}

// Phase 3 (fused): d in smem + smem-staged loss pass. A == 18.
__global__ void __launch_bounds__(BT) k_fused18(const float* __restrict__ w,
                                                const float* __restrict__ r,
                                                const int* __restrict__ as,
                                                long long T) {
    __shared__ float  sd[FCHUNK];            // 8 KB
    __shared__ float2 st[AH * BT];           // 18 KB weight tile
    __shared__ float  shg[BT / 32], shs[BT / 32];
    int tid = threadIdx.x;
    long long cbase = (long long)blockIdx.x * FCHUNK;
    long long base = cbase + (long long)tid * FPT;

    // --- scan replay for this chunk ---
    float rv[FPT];
    load8(r, base, T, rv);
    int cnt = (int)max(0LL, min((long long)FPT, T - base));
    float carry = 0.0f;
    #pragma unroll
    for (int j = FPT - 1; j >= 0; --j) carry = carry * GAMMA + rv[j];
    float gseg = (cnt == FPT) ? gamma8() : __powf(GAMMA, (float)cnt);
    float tc = thread_carry(gseg, carry, g_cin[blockIdx.x], shg, shs);

    double dsum = 0.0;
    {
        float c2 = tc;
        if (cnt == FPT) {
            float dloc[FPT];
            #pragma unroll
            for (int j = FPT - 1; j >= 0; --j) { c2 = c2 * GAMMA + rv[j]; dloc[j] = c2; }
            #pragma unroll
            for (int j = 0; j < FPT; j++) { sd[tid * FPT + j] = dloc[j]; dsum += (double)dloc[j]; }
        } else {
            for (int j = FPT - 1; j >= 0; --j) {
                if (j < cnt) { c2 = c2 * GAMMA + rv[j]; sd[tid * FPT + j] = c2; dsum += (double)c2; }
                else sd[tid * FPT + j] = 0.0f;
            }
        }
    }

    // --- loss pass: 8 tiles of 256 rows, weight staged coalesced in smem ---
    const float2* w2 = reinterpret_cast<const float2*>(w);  // row t at w2[t*AH]
    long long n2 = T * AH;                                   // total float2 count
    double pn = 0.0, pp = 0.0;

    #pragma unroll
    for (int tile = 0; tile < FPT; tile++) {
        long long rbase = cbase + (long long)tile * BT;
        long long fbase = rbase * AH;
        __syncthreads();                 // protect sd (tile 0) / st reuse
        if (fbase + AH * BT <= n2) {
            #pragma unroll
            for (int i = 0; i < AH; i++)
                st[i * BT + tid] = __ldg(w2 + fbase + (long long)i * BT + tid);
        } else {
            #pragma unroll
            for (int i = 0; i < AH; i++) {
                long long idx = fbase + (long long)i * BT + tid;
                st[i * BT + tid] = (idx < n2) ? w2[idx] : make_float2(0.0f, 0.0f);
            }
        }
        __syncthreads();

        long long t = rbase + tid;
        if (t < T) {
            const float2* myrow = st + tid * AH;
            float s = 0.0f;
            #pragma unroll
            for (int i = 0; i < AH; i++) {
                float2 v = myrow[i];
                s += __expf(v.x);
                s += __expf(v.y);
            }
            int ai = as[t];
            float2 va = myrow[ai >> 1];
            float wa = (ai & 1) ? va.y : va.x;
            float nll = __logf(s) - wa;
            float d = sd[tile * BT + tid];
            pn += (double)nll;
            pp += (double)(nll * d);
        }
    }
    __syncthreads();
    block_reduce3(dsum, pn, pp);
}

// Generic-A fallback (direct loads)
__global__ void __launch_bounds__(BT) k_fused_gen(const float* __restrict__ w,
                                                  const float* __restrict__ r,
                                                  const int* __restrict__ as,
                                                  long long T, int A) {
    __shared__ float sd[FCHUNK];
    __shared__ float shg[BT / 32], shs[BT / 32];
    int tid = threadIdx.x;
    long long cbase = (long long)blockIdx.x * FCHUNK;
    long long base = cbase + (long long)tid * FPT;

    float rv[FPT];
    load8(r, base, T, rv);
    int cnt = (int)max(0LL, min((long long)FPT, T - base));
    float carry = 0.0f;
    #pragma unroll
    for (int j = FPT - 1; j >= 0; --j) carry = carry * GAMMA + rv[j];
    float gseg = (cnt == FPT) ? gamma8() : __powf(GAMMA, (float)cnt);
    float tc = thread_carry(gseg, carry, g_cin[blockIdx.x], shg, shs);

    double dsum = 0.0;
    {
        float c2 = tc;
        for (int j = FPT - 1; j >= 0; --j) {
            if (j < cnt) { c2 = c2 * GAMMA + rv[j]; sd[tid * FPT + j] = c2; dsum += (double)c2; }
            else sd[tid * FPT + j] = 0.0f;
        }
    }
    __syncthreads();

    double pn = 0.0, pp = 0.0;
    for (int j = 0; j < FPT; j++) {
        long long t = cbase + (long long)j * BT + tid;
        if (t < T) {
            const float* row = w + (size_t)t * A;
            float m = __ldg(row);
            for (int i = 1; i < A; i++) m = fmaxf(m, __ldg(row + i));
            float s = 0.0f;
            for (int i = 0; i < A; i++) s += __expf(__ldg(row + i) - m);
            int ai = as[t];
            float nll = m + __logf(s) - __ldg(row + ai);
            float d = sd[j * BT + tid];
            pn += (double)nll;
            pp += (double)(nll * d);
        }
    }
    block_reduce3(dsum, pn, pp);
}

__global__ void k_final(float* out, double Td) {
    double ds = g_acc[0], ns = g_acc[1], ps = g_acc[2];
    out[0] = (float)((ps - ds * ns / Td) / Td);
}

extern "C" void kernel_launch(void* const* d_in, const int* in_sizes, int n_in,
                              void* d_out, int out_size) {
    const float* w  = (const float*)d_in[0];   // [T, A]
    const float* r  = (const float*)d_in[1];   // [T]
    const int*   as = (const int*)d_in[2];     // [T] int32
    long long T = (long long)in_sizes[1];
    int A = (int)((long long)in_sizes[0] / T);
    long long NCll = (T + FCHUNK - 1) / FCHUNK;
    if (NCll > MAXC) NCll = MAXC;
    int NC = (int)NCll;

    k_agg<<<NC, BT>>>(r, T);
    k_scan2<<<1, BT>>>(NC);
    if (A == 18) k_fused18<<<NC, BT>>>(w, r, as, T);
    else         k_fused_gen<<<NC, BT>>>(w, r, as, T, A);
    k_final<<<1, 1>>>((float*)d_out, (double)T);
}

// round 9
// speedup vs baseline: 1.2930x; 1.2930x over previous
#include <cuda_runtime.h>
#include <cstdint>
#include <math.h>

// ---------------------------------------------------------------------------
// PolicyGradientLoss: out = mean( nll(w,a) * (D - mean D) )
//   D[t] = sum_{k>=t} gamma^{k-t} r[k]       (reverse affine scan)
//   nll[t] = logsumexp(w[t,:]) - w[t, a[t]]
// Identity: mean(nll*(D-mD)) = (S_pd - S_d*S_n/T)/T
// ep_as is int32 on device.
//
// R9 (= R8 + missing <cstdint>): cp.async double-buffered weight staging
// (coalesced, latency-hidden), smem-served logsumexp + gather, last-block
// ticket folds the finalize.
// ---------------------------------------------------------------------------

#define GAMMA 0.99f
#define BT 256                          // threads per block
#define FPT 8                           // tiles per block / rows per thread (scan)
#define FCHUNK (BT * FPT)               // 2048 rows per block
#define MAXT (1 << 22)
#define MAXC (MAXT / FCHUNK)
#define AH 9                            // float2 per row (A = 18)
#define ROWB 72                         // bytes per row
#define TBYTES (BT * ROWB)              // 18432 B per tile
#define NG16 (TBYTES / 16)              // 1152 16B granules per tile

static __device__ float  g_cg[MAXC];
static __device__ float  g_cs[MAXC];
static __device__ float  g_cin[MAXC];
static __device__ double g_acc[3];      // [0]=sum d, [1]=sum nll, [2]=sum nll*d
static __device__ unsigned int g_ctr;   // finish ticket

__device__ __forceinline__ float gamma8() {
    float g2 = GAMMA * GAMMA; float g4 = g2 * g2; return g4 * g4;
}

__device__ __forceinline__ void cp16(unsigned int saddr, const void* gptr) {
    asm volatile("cp.async.cg.shared.global [%0], [%1], 16;"
                 :: "r"(saddr), "l"(gptr) : "memory");
}
__device__ __forceinline__ void cp_commit() {
    asm volatile("cp.async.commit_group;" ::: "memory");
}
template <int N>
__device__ __forceinline__ void cp_wait() {
    asm volatile("cp.async.wait_group %0;" :: "n"(N) : "memory");
}

__device__ __forceinline__ void load8(const float* __restrict__ r, long long base,
                                      long long T, float rv[FPT]) {
    if (base + FPT <= T) {
        const float4* p = reinterpret_cast<const float4*>(r + base);
        float4 v0 = p[0], v1 = p[1];
        rv[0]=v0.x; rv[1]=v0.y; rv[2]=v0.z; rv[3]=v0.w;
        rv[4]=v1.x; rv[5]=v1.y; rv[6]=v1.z; rv[7]=v1.w;
    } else {
        #pragma unroll
        for (int j = 0; j < FPT; j++)
            rv[j] = (base + j < T) ? r[base + j] : 0.0f;
    }
}

// Warp inclusive suffix scan of affine (g,s): lane i -> aggregate [i..31].
__device__ __forceinline__ void warp_suffix_incl(float& g, float& s) {
    int lane = threadIdx.x & 31;
    #pragma unroll
    for (int off = 1; off < 32; off <<= 1) {
        float g2 = __shfl_down_sync(0xffffffffu, g, off);
        float s2 = __shfl_down_sync(0xffffffffu, s, off);
        if (lane + off < 32) { s = s + g * s2; g = g * g2; }
    }
}

// Carry value entering this thread's segment given block-incoming carry cin.
// Leaves shg/shs holding warp aggregates.
__device__ __forceinline__ float thread_carry(float gseg, float sseg, float cin,
                                              float* shg, float* shs) {
    int lane = threadIdx.x & 31, wid = threadIdx.x >> 5;
    int nw = blockDim.x >> 5;
    float g = gseg, s = sseg;
    warp_suffix_incl(g, s);
    float ge = __shfl_down_sync(0xffffffffu, g, 1);
    float se = __shfl_down_sync(0xffffffffu, s, 1);
    if (lane == 31) { ge = 1.0f; se = 0.0f; }
    if (lane == 0) { shg[wid] = g; shs[wid] = s; }
    __syncthreads();
    float gw = 1.0f, sw = 0.0f;
    for (int wv = wid + 1; wv < nw; wv++) { sw = sw + gw * shs[wv]; gw = gw * shg[wv]; }
    return se + ge * (sw + gw * cin);
}

__device__ __forceinline__ void block_reduce3(double a, double b, double c) {
    #pragma unroll
    for (int o = 16; o > 0; o >>= 1) {
        a += __shfl_down_sync(0xffffffffu, a, o);
        b += __shfl_down_sync(0xffffffffu, b, o);
        c += __shfl_down_sync(0xffffffffu, c, o);
    }
    __shared__ double sa[8], sb[8], sc[8];
    int lane = threadIdx.x & 31, wid = threadIdx.x >> 5;
    if (lane == 0) { sa[wid] = a; sb[wid] = b; sc[wid] = c; }
    __syncthreads();
    if (wid == 0) {
        int nw = blockDim.x >> 5;
        a = (lane < nw) ? sa[lane] : 0.0;
        b = (lane < nw) ? sb[lane] : 0.0;
        c = (lane < nw) ? sc[lane] : 0.0;
        #pragma unroll
        for (int o = 4; o > 0; o >>= 1) {
            a += __shfl_down_sync(0xffffffffu, a, o);
            b += __shfl_down_sync(0xffffffffu, b, o);
            c += __shfl_down_sync(0xffffffffu, c, o);
        }
        if (lane == 0) {
            atomicAdd(&g_acc[0], a);
            atomicAdd(&g_acc[1], b);
            atomicAdd(&g_acc[2], c);
        }
    }
}

// Last-block finalize (call after block_reduce3; tid 0 only acts)
__device__ __forceinline__ void finalize_if_last(float* out, long long T) {
    if (threadIdx.x == 0) {
        __threadfence();
        if (atomicAdd(&g_ctr, 1u) == gridDim.x - 1) {
            double Td = (double)T;
            double ds = g_acc[0], ns = g_acc[1], ps = g_acc[2];
            out[0] = (float)((ps - ds * ns / Td) / Td);
        }
    }
}

// Phase 1: per-chunk (g, s) aggregates
__global__ void __launch_bounds__(BT) k_agg(const float* __restrict__ r, long long T) {
    __shared__ float shg[BT / 32], shs[BT / 32];
    int tid = threadIdx.x;
    long long base = (long long)blockIdx.x * FCHUNK + (long long)tid * FPT;
    float rv[FPT];
    load8(r, base, T, rv);
    int cnt = (int)max(0LL, min((long long)FPT, T - base));
    float carry = 0.0f;
    #pragma unroll
    for (int j = FPT - 1; j >= 0; --j) carry = carry * GAMMA + rv[j];
    float gseg = (cnt == FPT) ? gamma8() : __powf(GAMMA, (float)cnt);
    (void)thread_carry(gseg, carry, 0.0f, shg, shs);
    __syncthreads();
    if (tid == 0) {
        int nw = blockDim.x >> 5;
        float g = 1.0f, s = 0.0f;
        for (int wv = 0; wv < nw; wv++) { s = s + g * shs[wv]; g = g * shg[wv]; }
        g_cg[blockIdx.x] = g; g_cs[blockIdx.x] = s;
    }
}

// Phase 2: suffix scan over chunk aggregates; zeroes accumulators/ticket.
__global__ void __launch_bounds__(BT) k_scan2(int nchunk) {
    __shared__ float shg[BT / 32], shs[BT / 32];
    int tid = threadIdx.x;
    if (tid == 0) { g_acc[0] = 0.0; g_acc[1] = 0.0; g_acc[2] = 0.0; g_ctr = 0u; }
    int kc = (nchunk + BT - 1) / BT;
    int lo = tid * kc;
    int hi = min(lo + kc, nchunk);
    float g = 1.0f, s = 0.0f;
    for (int c = lo; c < hi; c++) { s = s + g * g_cs[c]; g = g * g_cg[c]; }
    float carry = thread_carry(g, s, 0.0f, shg, shs);
    for (int c = hi - 1; c >= lo; --c) {
        g_cin[c] = carry;
        carry = g_cs[c] + g_cg[c] * carry;
    }
}

// Phase 3 (fused): scan replay + cp.async double-buffered loss. A == 18.
__global__ void __launch_bounds__(BT) k_fused18(const float* __restrict__ w,
                                                const float* __restrict__ r,
                                                const int* __restrict__ as,
                                                long long T, float* out) {
    __shared__ float sd[FCHUNK];                          // 8 KB
    __shared__ __align__(16) char wbuf[2][TBYTES];        // 36 KB
    __shared__ float shg[BT / 32], shs[BT / 32];
    int tid = threadIdx.x;
    long long cbase = (long long)blockIdx.x * FCHUNK;
    bool full = (cbase + FCHUNK <= T);
    const char* wg = reinterpret_cast<const char*>(w) + cbase * ROWB;

    unsigned int sb0 = (unsigned int)__cvta_generic_to_shared(wbuf[0]);
    unsigned int sb1 = (unsigned int)__cvta_generic_to_shared(wbuf[1]);

    // kick off tile 0 copy before doing the scan work
    if (full) {
        #pragma unroll
        for (int i = tid; i < NG16; i += BT)
            cp16(sb0 + i * 16, wg + (long long)i * 16);
        cp_commit();
    }

    // --- scan replay for this chunk ---
    long long base = cbase + (long long)tid * FPT;
    float rv[FPT];
    load8(r, base, T, rv);
    int cnt = (int)max(0LL, min((long long)FPT, T - base));
    float carry = 0.0f;
    #pragma unroll
    for (int j = FPT - 1; j >= 0; --j) carry = carry * GAMMA + rv[j];
    float gseg = (cnt == FPT) ? gamma8() : __powf(GAMMA, (float)cnt);
    float tc = thread_carry(gseg, carry, g_cin[blockIdx.x], shg, shs);

    double dsum = 0.0;
    {
        float c2 = tc;
        if (cnt == FPT) {
            float dloc[FPT];
            #pragma unroll
            for (int j = FPT - 1; j >= 0; --j) { c2 = c2 * GAMMA + rv[j]; dloc[j] = c2; }
            #pragma unroll
            for (int j = 0; j < FPT; j++) { sd[tid * FPT + j] = dloc[j]; dsum += (double)dloc[j]; }
        } else {
            for (int j = FPT - 1; j >= 0; --j) {
                if (j < cnt) { c2 = c2 * GAMMA + rv[j]; sd[tid * FPT + j] = c2; dsum += (double)c2; }
                else sd[tid * FPT + j] = 0.0f;
            }
        }
    }
    __syncthreads();   // sd visible

    double pn = 0.0, pp = 0.0;

    if (full) {
        #pragma unroll
        for (int tile = 0; tile < FPT; tile++) {
            // prefetch next tile into the other buffer (free: its last reader
            // finished at the end-of-previous-iteration barrier)
            if (tile + 1 < FPT) {
                unsigned int dst = ((tile + 1) & 1) ? sb1 : sb0;
                const char* src = wg + (long long)(tile + 1) * TBYTES;
                #pragma unroll
                for (int i = tid; i < NG16; i += BT)
                    cp16(dst + i * 16, src + (long long)i * 16);
                cp_commit();
            }
            if (tile + 1 < FPT) cp_wait<1>(); else cp_wait<0>();
            __syncthreads();           // tile's buffer fully visible

            const float2* st = reinterpret_cast<const float2*>(wbuf[tile & 1]);
            long long t = cbase + (long long)tile * BT + tid;
            const float2* myrow = st + tid * AH;
            float s0 = 0.0f, s1 = 0.0f;
            #pragma unroll
            for (int i = 0; i < AH; i++) {
                float2 v = myrow[i];
                s0 += __expf(v.x);
                s1 += __expf(v.y);
            }
            int ai = as[t];
            float2 va = myrow[ai >> 1];
            float wa = (ai & 1) ? va.y : va.x;
            float nll = __logf(s0 + s1) - wa;
            float d = sd[tile * BT + tid];
            pn += (double)nll;
            pp += (double)(nll * d);

            __syncthreads();           // done reading before buffer reuse
        }
    } else {
        // partial last chunk: direct strided loads (at most one block)
        for (int tile = 0; tile < FPT; tile++) {
            long long t = cbase + (long long)tile * BT + tid;
            if (t < T) {
                const float* row = w + (size_t)t * (AH * 2);
                const float2* p2 = reinterpret_cast<const float2*>(row);
                float s = 0.0f;
                #pragma unroll
                for (int i = 0; i < AH; i++) {
                    float2 v = __ldg(p2 + i);
                    s += __expf(v.x) + __expf(v.y);
                }
                int ai = as[t];
                float nll = __logf(s) - __ldg(row + ai);
                float d = sd[tile * BT + tid];
                pn += (double)nll;
                pp += (double)(nll * d);
            }
        }
        __syncthreads();
    }

    block_reduce3(dsum, pn, pp);
    finalize_if_last(out, T);
}

// Generic-A fallback (direct loads)
__global__ void __launch_bounds__(BT) k_fused_gen(const float* __restrict__ w,
                                                  const float* __restrict__ r,
                                                  const int* __restrict__ as,
                                                  long long T, int A, float* out) {
    __shared__ float sd[FCHUNK];
    __shared__ float shg[BT / 32], shs[BT / 32];
    int tid = threadIdx.x;
    long long cbase = (long long)blockIdx.x * FCHUNK;
    long long base = cbase + (long long)tid * FPT;

    float rv[FPT];
    load8(r, base, T, rv);
    int cnt = (int)max(0LL, min((long long)FPT, T - base));
    float carry = 0.0f;
    #pragma unroll
    for (int j = FPT - 1; j >= 0; --j) carry = carry * GAMMA + rv[j];
    float gseg = (cnt == FPT) ? gamma8() : __powf(GAMMA, (float)cnt);
    float tc = thread_carry(gseg, carry, g_cin[blockIdx.x], shg, shs);

    double dsum = 0.0;
    {
        float c2 = tc;
        for (int j = FPT - 1; j >= 0; --j) {
            if (j < cnt) { c2 = c2 * GAMMA + rv[j]; sd[tid * FPT + j] = c2; dsum += (double)c2; }
            else sd[tid * FPT + j] = 0.0f;
        }
    }
    __syncthreads();

    double pn = 0.0, pp = 0.0;
    for (int j = 0; j < FPT; j++) {
        long long t = cbase + (long long)j * BT + tid;
        if (t < T) {
            const float* row = w + (size_t)t * A;
            float m = __ldg(row);
            for (int i = 1; i < A; i++) m = fmaxf(m, __ldg(row + i));
            float s = 0.0f;
            for (int i = 0; i < A; i++) s += __expf(__ldg(row + i) - m);
            int ai = as[t];
            float nll = m + __logf(s) - __ldg(row + ai);
            float d = sd[j * BT + tid];
            pn += (double)nll;
            pp += (double)(nll * d);
        }
    }
    block_reduce3(dsum, pn, pp);
    finalize_if_last(out, T);
}

extern "C" void kernel_launch(void* const* d_in, const int* in_sizes, int n_in,
                              void* d_out, int out_size) {
    const float* w  = (const float*)d_in[0];   // [T, A]
    const float* r  = (const float*)d_in[1];   // [T]
    const int*   as = (const int*)d_in[2];     // [T] int32
    long long T = (long long)in_sizes[1];
    int A = (int)((long long)in_sizes[0] / T);
    long long NCll = (T + FCHUNK - 1) / FCHUNK;
    if (NCll > MAXC) NCll = MAXC;
    int NC = (int)NCll;

    k_agg<<<NC, BT>>>(r, T);
    k_scan2<<<1, BT>>>(NC);
    if (A == 18) k_fused18<<<NC, BT>>>(w, r, as, T, (float*)d_out);
    else         k_fused_gen<<<NC, BT>>>(w, r, as, T, A, (float*)d_out);
}

// round 11
// speedup vs baseline: 1.5903x; 1.2299x over previous
#include <cuda_runtime.h>
#include <cstdint>
#include <math.h>

// ---------------------------------------------------------------------------
// PolicyGradientLoss: out = mean( nll(w,a) * (D - mean D) )
//   D[t] = sum_{k>=t} gamma^{k-t} r[k]       (reverse affine scan)
//   nll[t] = logsumexp(w[t,:]) - w[t, a[t]]
// Identity: mean(nll*(D-mD)) = (S_pd - S_d*S_n/T)/T
// ep_as is int32 on device.
//
// R11 (= R10 + shadowed-variable fix): (1) float per-thread accumulators
// (FP64 pipe was co-binding ~25us), doubles only at block reduce; (2) 3-buffer
// cp.async ring, depth-2 prefetch (dynamic smem 62KB); (3) two launches:
// k_agg(+scan2 ticket) and k_fused(+finalize ticket).
// ---------------------------------------------------------------------------

#define GAMMA 0.99f
#define BT 256                          // threads per block
#define FPT 8                           // tiles per block / rows per thread (scan)
#define FCHUNK (BT * FPT)               // 2048 rows per block
#define MAXT (1 << 22)
#define MAXC (MAXT / FCHUNK)
#define AH 9                            // float2 per row (A = 18)
#define ROWB 72                         // bytes per row
#define TBYTES (BT * ROWB)              // 18432 B per tile (256 rows)
#define NG16 (TBYTES / 16)              // 1152 16B granules per tile
#define NBUF 3
#define PRE 2
#define DYNBYTES (NBUF * TBYTES + FCHUNK * 4)   // 55296 + 8192 = 63488

static __device__ float  g_cg[MAXC];
static __device__ float  g_cs[MAXC];
static __device__ float  g_cin[MAXC];
static __device__ double g_acc[3];      // [0]=sum d, [1]=sum nll, [2]=sum nll*d
static __device__ unsigned int g_ctr;   // fused finish ticket
static __device__ unsigned int g_ctr2;  // agg finish ticket

__device__ __forceinline__ float gamma8() {
    float g2 = GAMMA * GAMMA; float g4 = g2 * g2; return g4 * g4;
}

__device__ __forceinline__ void cp16(unsigned int saddr, const void* gptr) {
    asm volatile("cp.async.cg.shared.global [%0], [%1], 16;"
                 :: "r"(saddr), "l"(gptr) : "memory");
}
__device__ __forceinline__ void cp_commit() {
    asm volatile("cp.async.commit_group;" ::: "memory");
}
template <int N>
__device__ __forceinline__ void cp_wait() {
    asm volatile("cp.async.wait_group %0;" :: "n"(N) : "memory");
}

__device__ __forceinline__ void load8(const float* __restrict__ r, long long base,
                                      long long T, float rv[FPT]) {
    if (base + FPT <= T) {
        const float4* p = reinterpret_cast<const float4*>(r + base);
        float4 v0 = p[0], v1 = p[1];
        rv[0]=v0.x; rv[1]=v0.y; rv[2]=v0.z; rv[3]=v0.w;
        rv[4]=v1.x; rv[5]=v1.y; rv[6]=v1.z; rv[7]=v1.w;
    } else {
        #pragma unroll
        for (int j = 0; j < FPT; j++)
            rv[j] = (base + j < T) ? r[base + j] : 0.0f;
    }
}

// Warp inclusive suffix scan of affine (g,s): lane i -> aggregate [i..31].
__device__ __forceinline__ void warp_suffix_incl(float& g, float& s) {
    int lane = threadIdx.x & 31;
    #pragma unroll
    for (int off = 1; off < 32; off <<= 1) {
        float g2 = __shfl_down_sync(0xffffffffu, g, off);
        float s2 = __shfl_down_sync(0xffffffffu, s, off);
        if (lane + off < 32) { s = s + g * s2; g = g * g2; }
    }
}

// Carry entering this thread's segment given block-incoming carry cin.
__device__ __forceinline__ float thread_carry(float gseg, float sseg, float cin,
                                              float* shg, float* shs) {
    int lane = threadIdx.x & 31, wid = threadIdx.x >> 5;
    int nw = blockDim.x >> 5;
    float g = gseg, s = sseg;
    warp_suffix_incl(g, s);
    float ge = __shfl_down_sync(0xffffffffu, g, 1);
    float se = __shfl_down_sync(0xffffffffu, s, 1);
    if (lane == 31) { ge = 1.0f; se = 0.0f; }
    if (lane == 0) { shg[wid] = g; shs[wid] = s; }
    __syncthreads();
    float gw = 1.0f, sw = 0.0f;
    for (int wv = wid + 1; wv < nw; wv++) { sw = sw + gw * shs[wv]; gw = gw * shg[wv]; }
    return se + ge * (sw + gw * cin);
}

// Float warp reduce -> per-warp double partial -> warp0 double reduce -> atomics
__device__ __forceinline__ void block_reduce3f(float a, float b, float c) {
    #pragma unroll
    for (int o = 16; o > 0; o >>= 1) {
        a += __shfl_down_sync(0xffffffffu, a, o);
        b += __shfl_down_sync(0xffffffffu, b, o);
        c += __shfl_down_sync(0xffffffffu, c, o);
    }
    __shared__ double sa[8], sb[8], sc[8];
    int lane = threadIdx.x & 31, wid = threadIdx.x >> 5;
    if (lane == 0) { sa[wid] = (double)a; sb[wid] = (double)b; sc[wid] = (double)c; }
    __syncthreads();
    if (wid == 0) {
        int nw = blockDim.x >> 5;
        double da = (lane < nw) ? sa[lane] : 0.0;
        double db = (lane < nw) ? sb[lane] : 0.0;
        double dc = (lane < nw) ? sc[lane] : 0.0;
        #pragma unroll
        for (int o = 4; o > 0; o >>= 1) {
            da += __shfl_down_sync(0xffffffffu, da, o);
            db += __shfl_down_sync(0xffffffffu, db, o);
            dc += __shfl_down_sync(0xffffffffu, dc, o);
        }
        if (lane == 0) {
            atomicAdd(&g_acc[0], da);
            atomicAdd(&g_acc[1], db);
            atomicAdd(&g_acc[2], dc);
        }
    }
}

// ---------------------------------------------------------------------------
// Kernel 1: per-chunk aggregates; last-finished block runs the chunk scan,
// zeroes accumulators and tickets.
// ---------------------------------------------------------------------------
__global__ void __launch_bounds__(BT) k_agg(const float* __restrict__ r, long long T) {
    __shared__ float shg[BT / 32], shs[BT / 32];
    __shared__ int is_last;
    int tid = threadIdx.x;
    int nchunk = gridDim.x;
    long long base = (long long)blockIdx.x * FCHUNK + (long long)tid * FPT;
    float rv[FPT];
    load8(r, base, T, rv);
    int cnt = (int)max(0LL, min((long long)FPT, T - base));
    float carry = 0.0f;
    #pragma unroll
    for (int j = FPT - 1; j >= 0; --j) carry = carry * GAMMA + rv[j];
    float gseg = (cnt == FPT) ? gamma8() : __powf(GAMMA, (float)cnt);
    (void)thread_carry(gseg, carry, 0.0f, shg, shs);
    __syncthreads();
    if (tid == 0) {
        int nw = blockDim.x >> 5;
        float g = 1.0f, s = 0.0f;
        for (int wv = 0; wv < nw; wv++) { s = s + g * shs[wv]; g = g * shg[wv]; }
        g_cg[blockIdx.x] = g; g_cs[blockIdx.x] = s;
        __threadfence();
        is_last = (atomicAdd(&g_ctr2, 1u) == (unsigned)nchunk - 1u) ? 1 : 0;
    }
    __syncthreads();
    if (!is_last) return;

    // --- last block: suffix scan over chunk aggregates + housekeeping ---
    __threadfence();   // acquire the other blocks' g_cg/g_cs
    if (tid == 0) { g_acc[0] = 0.0; g_acc[1] = 0.0; g_acc[2] = 0.0;
                    g_ctr = 0u; g_ctr2 = 0u; }
    __syncthreads();   // reuse shg/shs safely
    int kc = (nchunk + BT - 1) / BT;
    int lo = tid * kc;
    int hi = min(lo + kc, nchunk);
    float cg = 1.0f, cs = 0.0f;
    for (int c = lo; c < hi; c++) { cs = cs + cg * g_cs[c]; cg = cg * g_cg[c]; }
    float scarry = thread_carry(cg, cs, 0.0f, shg, shs);
    for (int c = hi - 1; c >= lo; --c) {
        g_cin[c] = scarry;
        scarry = g_cs[c] + g_cg[c] * scarry;
    }
}

// ---------------------------------------------------------------------------
// Kernel 2 (fused): scan replay + 3-buffer cp.async ring loss; last-block
// ticket computes the final scalar. A == 18 specialization.
// ---------------------------------------------------------------------------
__global__ void __launch_bounds__(BT) k_fused18(const float* __restrict__ w,
                                                const float* __restrict__ r,
                                                const int* __restrict__ as,
                                                long long T, float* out) {
    extern __shared__ __align__(16) char dyns[];
    char*  wbuf = dyns;                                  // NBUF * TBYTES
    float* sd   = reinterpret_cast<float*>(dyns + NBUF * TBYTES);  // FCHUNK
    __shared__ float shg[BT / 32], shs[BT / 32];
    int tid = threadIdx.x;
    long long cbase = (long long)blockIdx.x * FCHUNK;
    bool full = (cbase + FCHUNK <= T);
    const char* wg = reinterpret_cast<const char*>(w) + cbase * ROWB;

    unsigned int sb[NBUF];
    #pragma unroll
    for (int b = 0; b < NBUF; b++)
        sb[b] = (unsigned int)__cvta_generic_to_shared(wbuf + b * TBYTES);

    // prologue: issue tiles 0..PRE-1
    if (full) {
        #pragma unroll
        for (int k = 0; k < PRE; k++) {
            #pragma unroll
            for (int i = tid; i < NG16; i += BT)
                cp16(sb[k] + i * 16, wg + (long long)k * TBYTES + (long long)i * 16);
            cp_commit();
        }
    }

    // --- scan replay for this chunk (overlaps with prologue copies) ---
    long long base = cbase + (long long)tid * FPT;
    float rv[FPT];
    load8(r, base, T, rv);
    int cnt = (int)max(0LL, min((long long)FPT, T - base));
    float carry = 0.0f;
    #pragma unroll
    for (int j = FPT - 1; j >= 0; --j) carry = carry * GAMMA + rv[j];
    float gseg = (cnt == FPT) ? gamma8() : __powf(GAMMA, (float)cnt);
    float tc = thread_carry(gseg, carry, g_cin[blockIdx.x], shg, shs);

    float dsum = 0.0f;
    {
        float c2 = tc;
        if (cnt == FPT) {
            float dloc[FPT];
            #pragma unroll
            for (int j = FPT - 1; j >= 0; --j) { c2 = c2 * GAMMA + rv[j]; dloc[j] = c2; }
            #pragma unroll
            for (int j = 0; j < FPT; j++) { sd[tid * FPT + j] = dloc[j]; dsum += dloc[j]; }
        } else {
            for (int j = FPT - 1; j >= 0; --j) {
                if (j < cnt) { c2 = c2 * GAMMA + rv[j]; sd[tid * FPT + j] = c2; dsum += c2; }
                else sd[tid * FPT + j] = 0.0f;
            }
        }
    }
    __syncthreads();   // sd visible

    float pn = 0.0f, pp = 0.0f;

    if (full) {
        #pragma unroll
        for (int tile = 0; tile < FPT; tile++) {
            // wait for tile's group: pending after wait must exclude it
            if (tile + PRE <= FPT - 1) cp_wait<PRE - 1>(); else cp_wait<0>();
            __syncthreads();           // tile buffer fully visible to all

            const float2* st = reinterpret_cast<const float2*>(wbuf + (tile % NBUF) * TBYTES);
            long long t = cbase + (long long)tile * BT + tid;
            int ai = as[t];
            const float2* myrow = st + tid * AH;
            float s0 = 0.0f, s1 = 0.0f;
            #pragma unroll
            for (int i = 0; i < AH; i++) {
                float2 v = myrow[i];
                s0 += __expf(v.x);
                s1 += __expf(v.y);
            }
            float2 va = myrow[ai >> 1];
            float wa = (ai & 1) ? va.y : va.x;
            float nll = __logf(s0 + s1) - wa;
            float d = sd[tile * BT + tid];
            pn += nll;
            pp += nll * d;

            __syncthreads();           // all reads done before buffer reuse
            if (tile + PRE < FPT) {
                unsigned int dst = sb[(tile + PRE) % NBUF];
                const char* src = wg + (long long)(tile + PRE) * TBYTES;
                #pragma unroll
                for (int i = tid; i < NG16; i += BT)
                    cp16(dst + i * 16, src + (long long)i * 16);
                cp_commit();
            }
        }
    } else {
        // partial last chunk: direct loads (at most one block)
        for (int tile = 0; tile < FPT; tile++) {
            long long t = cbase + (long long)tile * BT + tid;
            if (t < T) {
                const float* row = w + (size_t)t * (AH * 2);
                const float2* p2 = reinterpret_cast<const float2*>(row);
                float s = 0.0f;
                #pragma unroll
                for (int i = 0; i < AH; i++) {
                    float2 v = __ldg(p2 + i);
                    s += __expf(v.x) + __expf(v.y);
                }
                int ai = as[t];
                float nll = __logf(s) - __ldg(row + ai);
                pn += nll;
                pp += nll * sd[tile * BT + tid];
            }
        }
        __syncthreads();
    }

    block_reduce3f(dsum, pn, pp);

    if (tid == 0) {
        __threadfence();
        if (atomicAdd(&g_ctr, 1u) == gridDim.x - 1) {
            __threadfence();
            double Td = (double)T;
            double ds = g_acc[0], ns = g_acc[1], ps = g_acc[2];
            out[0] = (float)((ps - ds * ns / Td) / Td);
            g_ctr = 0u;
        }
    }
}

// Generic-A fallback (direct loads, float accumulators)
__global__ void __launch_bounds__(BT) k_fused_gen(const float* __restrict__ w,
                                                  const float* __restrict__ r,
                                                  const int* __restrict__ as,
                                                  long long T, int A, float* out) {
    extern __shared__ __align__(16) char dyns[];
    float* sd = reinterpret_cast<float*>(dyns + NBUF * TBYTES);
    __shared__ float shg[BT / 32], shs[BT / 32];
    int tid = threadIdx.x;
    long long cbase = (long long)blockIdx.x * FCHUNK;
    long long base = cbase + (long long)tid * FPT;

    float rv[FPT];
    load8(r, base, T, rv);
    int cnt = (int)max(0LL, min((long long)FPT, T - base));
    float carry = 0.0f;
    #pragma unroll
    for (int j = FPT - 1; j >= 0; --j) carry = carry * GAMMA + rv[j];
    float gseg = (cnt == FPT) ? gamma8() : __powf(GAMMA, (float)cnt);
    float tc = thread_carry(gseg, carry, g_cin[blockIdx.x], shg, shs);

    float dsum = 0.0f;
    {
        float c2 = tc;
        for (int j = FPT - 1; j >= 0; --j) {
            if (j < cnt) { c2 = c2 * GAMMA + rv[j]; sd[tid * FPT + j] = c2; dsum += c2; }
            else sd[tid * FPT + j] = 0.0f;
        }
    }
    __syncthreads();

    float pn = 0.0f, pp = 0.0f;
    for (int j = 0; j < FPT; j++) {
        long long t = cbase + (long long)j * BT + tid;
        if (t < T) {
            const float* row = w + (size_t)t * A;
            float m = __ldg(row);
            for (int i = 1; i < A; i++) m = fmaxf(m, __ldg(row + i));
            float s = 0.0f;
            for (int i = 0; i < A; i++) s += __expf(__ldg(row + i) - m);
            int ai = as[t];
            float nll = m + __logf(s) - __ldg(row + ai);
            pn += nll;
            pp += nll * sd[j * BT + tid];
        }
    }
    block_reduce3f(dsum, pn, pp);

    if (tid == 0) {
        __threadfence();
        if (atomicAdd(&g_ctr, 1u) == gridDim.x - 1) {
            __threadfence();
            double Td = (double)T;
            double ds = g_acc[0], ns = g_acc[1], ps = g_acc[2];
            out[0] = (float)((ps - ds * ns / Td) / Td);
            g_ctr = 0u;
        }
    }
}

extern "C" void kernel_launch(void* const* d_in, const int* in_sizes, int n_in,
                              void* d_out, int out_size) {
    const float* w  = (const float*)d_in[0];   // [T, A]
    const float* r  = (const float*)d_in[1];   // [T]
    const int*   as = (const int*)d_in[2];     // [T] int32
    long long T = (long long)in_sizes[1];
    int A = (int)((long long)in_sizes[0] / T);
    long long NCll = (T + FCHUNK - 1) / FCHUNK;
    if (NCll > MAXC) NCll = MAXC;
    int NC = (int)NCll;

    static int attr_done = 0;
    if (!attr_done) {
        cudaFuncSetAttribute(k_fused18, cudaFuncAttributeMaxDynamicSharedMemorySize, DYNBYTES);
        cudaFuncSetAttribute(k_fused_gen, cudaFuncAttributeMaxDynamicSharedMemorySize, DYNBYTES);
        attr_done = 1;
    }

    k_agg<<<NC, BT>>>(r, T);
    if (A == 18) k_fused18<<<NC, BT, DYNBYTES>>>(w, r, as, T, (float*)d_out);
    else         k_fused_gen<<<NC, BT, DYNBYTES>>>(w, r, as, T, A, (float*)d_out);
}

// round 12
// speedup vs baseline: 1.7549x; 1.1035x over previous
#include <cuda_runtime.h>
#include <cstdint>
#include <math.h>

// ---------------------------------------------------------------------------
// PolicyGradientLoss: out = mean( nll(w,a) * (D - mean D) )
//   D[t] = sum_{k>=t} gamma^{k-t} r[k]       (reverse affine scan)
//   nll[t] = logsumexp(w[t,:]) - w[t, a[t]]
// Identity: mean(nll*(D-mD)) = (S_pd - S_d*S_n/T)/T
// ep_as is int32 on device.
//
// R12: occupancy push. NBUF=2/PRE=1 (smem 44KB -> 5 blocks/SM, occ 62.5%),
// single barrier per tile (wait -> sync -> issue next -> compute), float
// per-thread accumulators, two launches with finish tickets.
// ---------------------------------------------------------------------------

#define GAMMA 0.99f
#define BT 256                          // threads per block
#define FPT 8                           // tiles per block / rows per thread (scan)
#define FCHUNK (BT * FPT)               // 2048 rows per block
#define MAXT (1 << 22)
#define MAXC (MAXT / FCHUNK)
#define AH 9                            // float2 per row (A = 18)
#define ROWB 72                         // bytes per row
#define TBYTES (BT * ROWB)              // 18432 B per tile (256 rows)
#define NG16 (TBYTES / 16)              // 1152 16B granules per tile
#define NBUF 2
#define DYNBYTES (NBUF * TBYTES + FCHUNK * 4)   // 36864 + 8192 = 45056

static __device__ float  g_cg[MAXC];
static __device__ float  g_cs[MAXC];
static __device__ float  g_cin[MAXC];
static __device__ double g_acc[3];      // [0]=sum d, [1]=sum nll, [2]=sum nll*d
static __device__ unsigned int g_ctr;   // fused finish ticket
static __device__ unsigned int g_ctr2;  // agg finish ticket

__device__ __forceinline__ float gamma8() {
    float g2 = GAMMA * GAMMA; float g4 = g2 * g2; return g4 * g4;
}

__device__ __forceinline__ void cp16(unsigned int saddr, const void* gptr) {
    asm volatile("cp.async.cg.shared.global [%0], [%1], 16;"
                 :: "r"(saddr), "l"(gptr) : "memory");
}
__device__ __forceinline__ void cp_commit() {
    asm volatile("cp.async.commit_group;" ::: "memory");
}
template <int N>
__device__ __forceinline__ void cp_wait() {
    asm volatile("cp.async.wait_group %0;" :: "n"(N) : "memory");
}

__device__ __forceinline__ void load8(const float* __restrict__ r, long long base,
                                      long long T, float rv[FPT]) {
    if (base + FPT <= T) {
        const float4* p = reinterpret_cast<const float4*>(r + base);
        float4 v0 = p[0], v1 = p[1];
        rv[0]=v0.x; rv[1]=v0.y; rv[2]=v0.z; rv[3]=v0.w;
        rv[4]=v1.x; rv[5]=v1.y; rv[6]=v1.z; rv[7]=v1.w;
    } else {
        #pragma unroll
        for (int j = 0; j < FPT; j++)
            rv[j] = (base + j < T) ? r[base + j] : 0.0f;
    }
}

// Warp inclusive suffix scan of affine (g,s): lane i -> aggregate [i..31].
__device__ __forceinline__ void warp_suffix_incl(float& g, float& s) {
    int lane = threadIdx.x & 31;
    #pragma unroll
    for (int off = 1; off < 32; off <<= 1) {
        float g2 = __shfl_down_sync(0xffffffffu, g, off);
        float s2 = __shfl_down_sync(0xffffffffu, s, off);
        if (lane + off < 32) { s = s + g * s2; g = g * g2; }
    }
}

// Carry entering this thread's segment given block-incoming carry cin.
__device__ __forceinline__ float thread_carry(float gseg, float sseg, float cin,
                                              float* shg, float* shs) {
    int lane = threadIdx.x & 31, wid = threadIdx.x >> 5;
    int nw = blockDim.x >> 5;
    float g = gseg, s = sseg;
    warp_suffix_incl(g, s);
    float ge = __shfl_down_sync(0xffffffffu, g, 1);
    float se = __shfl_down_sync(0xffffffffu, s, 1);
    if (lane == 31) { ge = 1.0f; se = 0.0f; }
    if (lane == 0) { shg[wid] = g; shs[wid] = s; }
    __syncthreads();
    float gw = 1.0f, sw = 0.0f;
    for (int wv = wid + 1; wv < nw; wv++) { sw = sw + gw * shs[wv]; gw = gw * shg[wv]; }
    return se + ge * (sw + gw * cin);
}

// Float warp reduce -> per-warp double partial -> warp0 double reduce -> atomics
__device__ __forceinline__ void block_reduce3f(float a, float b, float c) {
    #pragma unroll
    for (int o = 16; o > 0; o >>= 1) {
        a += __shfl_down_sync(0xffffffffu, a, o);
        b += __shfl_down_sync(0xffffffffu, b, o);
        c += __shfl_down_sync(0xffffffffu, c, o);
    }
    __shared__ double sa[8], sb[8], sc[8];
    int lane = threadIdx.x & 31, wid = threadIdx.x >> 5;
    if (lane == 0) { sa[wid] = (double)a; sb[wid] = (double)b; sc[wid] = (double)c; }
    __syncthreads();
    if (wid == 0) {
        int nw = blockDim.x >> 5;
        double da = (lane < nw) ? sa[lane] : 0.0;
        double db = (lane < nw) ? sb[lane] : 0.0;
        double dc = (lane < nw) ? sc[lane] : 0.0;
        #pragma unroll
        for (int o = 4; o > 0; o >>= 1) {
            da += __shfl_down_sync(0xffffffffu, da, o);
            db += __shfl_down_sync(0xffffffffu, db, o);
            dc += __shfl_down_sync(0xffffffffu, dc, o);
        }
        if (lane == 0) {
            atomicAdd(&g_acc[0], da);
            atomicAdd(&g_acc[1], db);
            atomicAdd(&g_acc[2], dc);
        }
    }
}

// ---------------------------------------------------------------------------
// Kernel 1: per-chunk aggregates; last-finished block runs the chunk scan,
// zeroes accumulators and tickets.
// ---------------------------------------------------------------------------
__global__ void __launch_bounds__(BT) k_agg(const float* __restrict__ r, long long T) {
    __shared__ float shg[BT / 32], shs[BT / 32];
    __shared__ int is_last;
    int tid = threadIdx.x;
    int nchunk = gridDim.x;
    long long base = (long long)blockIdx.x * FCHUNK + (long long)tid * FPT;
    float rv[FPT];
    load8(r, base, T, rv);
    int cnt = (int)max(0LL, min((long long)FPT, T - base));
    float carry = 0.0f;
    #pragma unroll
    for (int j = FPT - 1; j >= 0; --j) carry = carry * GAMMA + rv[j];
    float gseg = (cnt == FPT) ? gamma8() : __powf(GAMMA, (float)cnt);
    (void)thread_carry(gseg, carry, 0.0f, shg, shs);
    __syncthreads();
    if (tid == 0) {
        int nw = blockDim.x >> 5;
        float g = 1.0f, s = 0.0f;
        for (int wv = 0; wv < nw; wv++) { s = s + g * shs[wv]; g = g * shg[wv]; }
        g_cg[blockIdx.x] = g; g_cs[blockIdx.x] = s;
        __threadfence();
        is_last = (atomicAdd(&g_ctr2, 1u) == (unsigned)nchunk - 1u) ? 1 : 0;
    }
    __syncthreads();
    if (!is_last) return;

    // --- last block: suffix scan over chunk aggregates + housekeeping ---
    __threadfence();   // acquire other blocks' g_cg/g_cs
    if (tid == 0) { g_acc[0] = 0.0; g_acc[1] = 0.0; g_acc[2] = 0.0;
                    g_ctr = 0u; g_ctr2 = 0u; }
    __syncthreads();   // reuse shg/shs safely
    int kc = (nchunk + BT - 1) / BT;
    int lo = tid * kc;
    int hi = min(lo + kc, nchunk);
    float cg = 1.0f, cs = 0.0f;
    for (int c = lo; c < hi; c++) { cs = cs + cg * g_cs[c]; cg = cg * g_cg[c]; }
    float scarry = thread_carry(cg, cs, 0.0f, shg, shs);
    for (int c = hi - 1; c >= lo; --c) {
        g_cin[c] = scarry;
        scarry = g_cs[c] + g_cg[c] * scarry;
    }
}

// ---------------------------------------------------------------------------
// Kernel 2 (fused): scan replay + 2-buffer cp.async ping-pong loss with one
// barrier per tile; last-block ticket computes the final scalar. A == 18.
// ---------------------------------------------------------------------------
__global__ void __launch_bounds__(BT) k_fused18(const float* __restrict__ w,
                                                const float* __restrict__ r,
                                                const int* __restrict__ as,
                                                long long T, float* out) {
    extern __shared__ __align__(16) char dyns[];
    char*  wbuf = dyns;                                            // NBUF*TBYTES
    float* sd   = reinterpret_cast<float*>(dyns + NBUF * TBYTES);  // FCHUNK
    __shared__ float shg[BT / 32], shs[BT / 32];
    int tid = threadIdx.x;
    long long cbase = (long long)blockIdx.x * FCHUNK;
    bool full = (cbase + FCHUNK <= T);
    const char* wg = reinterpret_cast<const char*>(w) + cbase * ROWB;

    unsigned int sb[NBUF];
    #pragma unroll
    for (int b = 0; b < NBUF; b++)
        sb[b] = (unsigned int)__cvta_generic_to_shared(wbuf + b * TBYTES);

    // prologue: issue tile 0
    if (full) {
        #pragma unroll
        for (int i = tid; i < NG16; i += BT)
            cp16(sb[0] + i * 16, wg + (long long)i * 16);
        cp_commit();
    }

    // --- scan replay for this chunk (overlaps with prologue copy) ---
    long long base = cbase + (long long)tid * FPT;
    float rv[FPT];
    load8(r, base, T, rv);
    int cnt = (int)max(0LL, min((long long)FPT, T - base));
    float carry = 0.0f;
    #pragma unroll
    for (int j = FPT - 1; j >= 0; --j) carry = carry * GAMMA + rv[j];
    float gseg = (cnt == FPT) ? gamma8() : __powf(GAMMA, (float)cnt);
    float tc = thread_carry(gseg, carry, g_cin[blockIdx.x], shg, shs);

    float dsum = 0.0f;
    {
        float c2 = tc;
        if (cnt == FPT) {
            float dloc[FPT];
            #pragma unroll
            for (int j = FPT - 1; j >= 0; --j) { c2 = c2 * GAMMA + rv[j]; dloc[j] = c2; }
            #pragma unroll
            for (int j = 0; j < FPT; j++) { sd[tid * FPT + j] = dloc[j]; dsum += dloc[j]; }
        } else {
            for (int j = FPT - 1; j >= 0; --j) {
                if (j < cnt) { c2 = c2 * GAMMA + rv[j]; sd[tid * FPT + j] = c2; dsum += c2; }
                else sd[tid * FPT + j] = 0.0f;
            }
        }
    }

    float pn = 0.0f, pp = 0.0f;

    if (full) {
        #pragma unroll
        for (int tile = 0; tile < FPT; tile++) {
            cp_wait<0>();              // tile's copy complete (only group pending)
            __syncthreads();           // buffer visible to all; prev tile's reads done

            // issue next tile into the other buffer (last read before this sync)
            if (tile + 1 < FPT) {
                unsigned int dst = sb[(tile + 1) & 1];
                const char* src = wg + (long long)(tile + 1) * TBYTES;
                #pragma unroll
                for (int i = tid; i < NG16; i += BT)
                    cp16(dst + i * 16, src + (long long)i * 16);
                cp_commit();
            }

            const float2* st = reinterpret_cast<const float2*>(wbuf + (tile & 1) * TBYTES);
            long long t = cbase + (long long)tile * BT + tid;
            int ai = as[t];
            const float2* myrow = st + tid * AH;
            float s0 = 0.0f, s1 = 0.0f;
            #pragma unroll
            for (int i = 0; i < AH; i++) {
                float2 v = myrow[i];
                s0 += __expf(v.x);
                s1 += __expf(v.y);
            }
            float2 va = myrow[ai >> 1];
            float wa = (ai & 1) ? va.y : va.x;
            float nll = __logf(s0 + s1) - wa;
            float d = sd[tile * BT + tid];
            pn += nll;
            pp += nll * d;
        }
        __syncthreads();               // all sd reads done before reduce smem reuse
    } else {
        __syncthreads();               // sd visible
        for (int tile = 0; tile < FPT; tile++) {
            long long t = cbase + (long long)tile * BT + tid;
            if (t < T) {
                const float* row = w + (size_t)t * (AH * 2);
                const float2* p2 = reinterpret_cast<const float2*>(row);
                float s = 0.0f;
                #pragma unroll
                for (int i = 0; i < AH; i++) {
                    float2 v = __ldg(p2 + i);
                    s += __expf(v.x) + __expf(v.y);
                }
                int ai = as[t];
                float nll = __logf(s) - __ldg(row + ai);
                pn += nll;
                pp += nll * sd[tile * BT + tid];
            }
        }
        __syncthreads();
    }

    block_reduce3f(dsum, pn, pp);

    if (tid == 0) {
        __threadfence();
        if (atomicAdd(&g_ctr, 1u) == gridDim.x - 1) {
            __threadfence();
            double Td = (double)T;
            double ds = g_acc[0], ns = g_acc[1], ps = g_acc[2];
            out[0] = (float)((ps - ds * ns / Td) / Td);
            g_ctr = 0u;
        }
    }
}

// Generic-A fallback (direct loads, float accumulators)
__global__ void __launch_bounds__(BT) k_fused_gen(const float* __restrict__ w,
                                                  const float* __restrict__ r,
                                                  const int* __restrict__ as,
                                                  long long T, int A, float* out) {
    extern __shared__ __align__(16) char dyns[];
    float* sd = reinterpret_cast<float*>(dyns + NBUF * TBYTES);
    __shared__ float shg[BT / 32], shs[BT / 32];
    int tid = threadIdx.x;
    long long cbase = (long long)blockIdx.x * FCHUNK;
    long long base = cbase + (long long)tid * FPT;

    float rv[FPT];
    load8(r, base, T, rv);
    int cnt = (int)max(0LL, min((long long)FPT, T - base));
    float carry = 0.0f;
    #pragma unroll
    for (int j = FPT - 1; j >= 0; --j) carry = carry * GAMMA + rv[j];
    float gseg = (cnt == FPT) ? gamma8() : __powf(GAMMA, (float)cnt);
    float tc = thread_carry(gseg, carry, g_cin[blockIdx.x], shg, shs);

    float dsum = 0.0f;
    {
        float c2 = tc;
        for (int j = FPT - 1; j >= 0; --j) {
            if (j < cnt) { c2 = c2 * GAMMA + rv[j]; sd[tid * FPT + j] = c2; dsum += c2; }
            else sd[tid * FPT + j] = 0.0f;
        }
    }
    __syncthreads();

    float pn = 0.0f, pp = 0.0f;
    for (int j = 0; j < FPT; j++) {
        long long t = cbase + (long long)j * BT + tid;
        if (t < T) {
            const float* row = w + (size_t)t * A;
            float m = __ldg(row);
            for (int i = 1; i < A; i++) m = fmaxf(m, __ldg(row + i));
            float s = 0.0f;
            for (int i = 0; i < A; i++) s += __expf(__ldg(row + i) - m);
            int ai = as[t];
            float nll = m + __logf(s) - __ldg(row + ai);
            pn += nll;
            pp += nll * sd[j * BT + tid];
        }
    }
    __syncthreads();
    block_reduce3f(dsum, pn, pp);

    if (tid == 0) {
        __threadfence();
        if (atomicAdd(&g_ctr, 1u) == gridDim.x - 1) {
            __threadfence();
            double Td = (double)T;
            double ds = g_acc[0], ns = g_acc[1], ps = g_acc[2];
            out[0] = (float)((ps - ds * ns / Td) / Td);
            g_ctr = 0u;
        }
    }
}

extern "C" void kernel_launch(void* const* d_in, const int* in_sizes, int n_in,
                              void* d_out, int out_size) {
    const float* w  = (const float*)d_in[0];   // [T, A]
    const float* r  = (const float*)d_in[1];   // [T]
    const int*   as = (const int*)d_in[2];     // [T] int32
    long long T = (long long)in_sizes[1];
    int A = (int)((long long)in_sizes[0] / T);
    long long NCll = (T + FCHUNK - 1) / FCHUNK;
    if (NCll > MAXC) NCll = MAXC;
    int NC = (int)NCll;

    static int attr_done = 0;
    if (!attr_done) {
        cudaFuncSetAttribute(k_fused18, cudaFuncAttributeMaxDynamicSharedMemorySize, DYNBYTES);
        cudaFuncSetAttribute(k_fused_gen, cudaFuncAttributeMaxDynamicSharedMemorySize, DYNBYTES);
        attr_done = 1;
    }

    k_agg<<<NC, BT>>>(r, T);
    if (A == 18) k_fused18<<<NC, BT, DYNBYTES>>>(w, r, as, T, (float*)d_out);
    else         k_fused_gen<<<NC, BT, DYNBYTES>>>(w, r, as, T, A, (float*)d_out);
}